// round 4
// baseline (speedup 1.0000x reference)
#include <cuda_runtime.h>
#include <cuda_fp16.h>

#define N_NODES_MAX 50000
#define N_EDGES_MAX 800000
#define NODE_ROW 128          // 4*MUL floats per node
#define OUT_ROW 256           // output floats per node
#define TABLE_N 512
#define XMIN (-8.0f)
#define XMAX (8.0f)
#define INV_SQRT3 0.57735026918962576f
#define OUT_SCALE 0.25f       // 1/sqrt(16)
#define SCAN_B 1024
#define MAX_SCAN_BLOCKS 64

// ---- static device scratch (no allocations allowed) ----
__device__ float  g_mix_raw[TABLE_N * 128];     // raw mix values (build stage)
__device__ float4 g_vals4[TABLE_N * 32];        // per (i0,lane): {m_s,m_t,m_v,m_p}
__device__ uint2  g_slp4[TABLE_N * 32];         // per (i0,lane): 4 x fp16 slopes
__device__ float4 g_nodeT[N_NODES_MAX * 32];    // per (node,lane): {s, v0, v1, v2}
__device__ int    g_counts[N_NODES_MAX];
__device__ int    g_rowptr[N_NODES_MAX + 1];
__device__ int    g_cursor[N_NODES_MAX];
__device__ int    g_btot[MAX_SCAN_BLOCKS];
__device__ int    g_ssort[N_EDGES_MAX];         // senders sorted by receiver
__device__ float4 g_easort[N_EDGES_MAX];        // edge_attrs sorted by receiver

// ---------------------------------------------------------------------------
// Table build: mix(x) for TABLE_N grid points. One block per x.
// Folds: *0.25 global scale; cols [32,64) *= INV_SQRT3 (tp_0e factor).
// ---------------------------------------------------------------------------
__global__ void build_table_kernel(const float* __restrict__ w0,
                                   const float* __restrict__ w1,
                                   const float* __restrict__ w2) {
    __shared__ float h0[64];
    __shared__ float h1[64];
    const int t = threadIdx.x;                     // 0..127
    const float dx = (XMAX - XMIN) / (float)(TABLE_N - 1);
    const float x = XMIN + dx * (float)blockIdx.x;

    if (t < 64) {
        float z = x * w0[t];
        h0[t] = z / (1.0f + expf(-z));
    }
    __syncthreads();
    if (t < 64) {
        float acc = 0.0f;
#pragma unroll 8
        for (int i = 0; i < 64; i++) acc = fmaf(h0[i], w1[i * 64 + t], acc);
        float z = acc * 0.125f;
        h1[t] = z / (1.0f + expf(-z));
    }
    __syncthreads();
    {
        float acc = 0.0f;
#pragma unroll 8
        for (int i = 0; i < 64; i++) acc = fmaf(h1[i], w2[i * 128 + t], acc);
        float m = acc * 0.125f * OUT_SCALE;
        if (t >= 32 && t < 64) m *= INV_SQRT3;
        g_mix_raw[blockIdx.x * 128 + t] = m;
    }
}

// Pack (value float4, slope half4) per (row, lane).
__global__ void pack_table_kernel() {
    int i = blockIdx.x * blockDim.x + threadIdx.x;   // 0 .. TABLE_N*32-1
    if (i >= TABLE_N * 32) return;
    const int row = i >> 5;
    const int lane = i & 31;
    const float* r0 = g_mix_raw + row * 128;
    const float* r1 = (row < TABLE_N - 1) ? r0 + 128 : r0;
    float vs = r0[lane],      vt = r0[32 + lane];
    float vv = r0[64 + lane], vp = r0[96 + lane];
    float ds = r1[lane] - vs,      dt = r1[32 + lane] - vt;
    float dv = r1[64 + lane] - vv, dp = r1[96 + lane] - vp;
    g_vals4[i] = make_float4(vs, vt, vv, vp);
    half2 lo = __floats2half2_rn(ds, dt);
    half2 hi = __floats2half2_rn(dv, dp);
    uint2 u;
    u.x = *(unsigned int*)&lo;
    u.y = *(unsigned int*)&hi;
    g_slp4[i] = u;
}

// Pre-transpose node feats: nodeT[n][lane] = {s[lane], v0, v1, v2}
__global__ void transpose_nodes_kernel(const float* __restrict__ nf, int n_nodes) {
    const int wid  = threadIdx.x >> 5;
    const int lane = threadIdx.x & 31;
    const int node = blockIdx.x * 8 + wid;
    if (node >= n_nodes) return;
    const float* r = nf + (size_t)node * NODE_ROW;
    float s  = __ldg(r + lane);
    float v0 = __ldg(r + 32 + 3 * lane);
    float v1 = __ldg(r + 33 + 3 * lane);
    float v2 = __ldg(r + 34 + 3 * lane);
    g_nodeT[(size_t)node * 32 + lane] = make_float4(s, v0, v1, v2);
}

// ---------------------------------------------------------------------------
// Counting sort of edges by receiver (CSR build) — fully parallel scan
// ---------------------------------------------------------------------------
__global__ void zero_counts_kernel(int n_nodes) {
    int i = blockIdx.x * blockDim.x + threadIdx.x;
    if (i < n_nodes) g_counts[i] = 0;
}

__global__ void hist_kernel(const int* __restrict__ receivers, int E) {
    int e = blockIdx.x * blockDim.x + threadIdx.x;
    if (e < E) atomicAdd(&g_counts[receivers[e]], 1);
}

__global__ void scan1_kernel(int n_nodes) {
    __shared__ int s[SCAN_B];
    const int t = threadIdx.x;
    const int gid = blockIdx.x * SCAN_B + t;
    int v = (gid < n_nodes) ? g_counts[gid] : 0;
    s[t] = v;
    __syncthreads();
    for (int d = 1; d < SCAN_B; d <<= 1) {
        int x = (t >= d) ? s[t - d] : 0;
        __syncthreads();
        s[t] += x;
        __syncthreads();
    }
    if (gid < n_nodes) g_rowptr[gid] = s[t] - v;     // block-local exclusive
    if (t == SCAN_B - 1) g_btot[blockIdx.x] = s[t];
}

__global__ void scan2_kernel(int nb) {
    __shared__ int s[MAX_SCAN_BLOCKS];
    const int t = threadIdx.x;
    int v = (t < nb) ? g_btot[t] : 0;
    s[t] = v;
    __syncthreads();
    for (int d = 1; d < MAX_SCAN_BLOCKS; d <<= 1) {
        int x = (t >= d) ? s[t - d] : 0;
        __syncthreads();
        s[t] += x;
        __syncthreads();
    }
    if (t < nb) g_btot[t] = s[t] - v;                // exclusive
}

__global__ void scan3_kernel(int n_nodes, int E) {
    int gid = blockIdx.x * blockDim.x + threadIdx.x;
    if (gid < n_nodes) {
        int r = g_rowptr[gid] + g_btot[gid >> 10];
        g_rowptr[gid] = r;
        g_cursor[gid] = r;
    }
    if (gid == 0) g_rowptr[n_nodes] = E;
}

// Scatter: sort the payload (sender id + edge attrs), not indices.
__global__ void scatter_kernel(const int* __restrict__ senders,
                               const int* __restrict__ receivers,
                               const float4* __restrict__ edge_attrs,
                               int E) {
    int e = blockIdx.x * blockDim.x + threadIdx.x;
    if (e < E) {
        int pos = atomicAdd(&g_cursor[receivers[e]], 1);
        g_ssort[pos]  = senders[e];
        g_easort[pos] = edge_attrs[e];
    }
}

// ---------------------------------------------------------------------------
// Aggregate: one warp per receiver node. Lane l owns channel l. Per edge:
// 1x LDG.128 node gather + 1x LDG.128 table values + 1x LDG.64 fp16 slopes
// + 2 broadcast loads. Register accumulation, one shared transpose, 8
// coalesced stores. Zero atomics.
// ---------------------------------------------------------------------------
__global__ void aggregate_kernel(float* __restrict__ out, int n_nodes) {
    __shared__ float sh[8][OUT_ROW];               // 8 warps x 256 floats = 8 KB
    const int wid  = threadIdx.x >> 5;
    const int lane = threadIdx.x & 31;
    const int node = blockIdx.x * 8 + wid;
    if (node >= n_nodes) return;

    const int start = __ldg(&g_rowptr[node]);
    const int end   = __ldg(&g_rowptr[node + 1]);

    float a_s = 0.f, a_t = 0.f;
    float av0 = 0.f, av1 = 0.f, av2 = 0.f;
    float ap0 = 0.f, ap1 = 0.f, ap2 = 0.f;

    const float inv_dx = (float)(TABLE_N - 1) / (XMAX - XMIN);

    for (int i = start; i < end; i++) {
        const int s = __ldg(&g_ssort[i]);
        const float4 ea = __ldg(&g_easort[i]);     // ea.x = ea0; (y,z,w) = ea1

        const float4 nf = __ldg(&g_nodeT[(size_t)s * 32 + lane]);
        const float s_e = nf.x, v0 = nf.y, v1 = nf.z, v2 = nf.w;

        float tt = (ea.x - XMIN) * inv_dx;
        tt = fminf(fmaxf(tt, 0.0f), (float)(TABLE_N - 1) - 1.0e-3f);
        const int i0 = (int)tt;
        const float f = tt - (float)i0;

        const float4 mv = __ldg(&g_vals4[i0 * 32 + lane]);
        const uint2  su = __ldg(&g_slp4[i0 * 32 + lane]);
        const float2 slo = __half22float2(*(const half2*)&su.x);
        const float2 shi = __half22float2(*(const half2*)&su.y);

        const float m_s = fmaf(slo.x, f, mv.x);
        const float m_t = fmaf(slo.y, f, mv.y);
        const float m_v = fmaf(shi.x, f, mv.z);
        const float m_p = fmaf(shi.y, f, mv.w);

        a_s = fmaf(s_e, m_s, a_s);
        const float dot3 = fmaf(v0, ea.y, fmaf(v1, ea.z, v2 * ea.w));
        a_t = fmaf(dot3, m_t, a_t);                // INV_SQRT3 folded into table
        av0 = fmaf(v0, m_v, av0);
        av1 = fmaf(v1, m_v, av1);
        av2 = fmaf(v2, m_v, av2);
        const float sp = s_e * m_p;
        ap0 = fmaf(sp, ea.y, ap0);
        ap1 = fmaf(sp, ea.z, ap1);
        ap2 = fmaf(sp, ea.w, ap2);
    }

    // Transpose once per node via shared (stride-3 stores: conflict-free)
    float* shw = sh[wid];
    shw[lane]               = a_s;
    shw[32 + lane]          = a_t;
    shw[64  + 3 * lane]     = av0;
    shw[64  + 3 * lane + 1] = av1;
    shw[64  + 3 * lane + 2] = av2;
    shw[160 + 3 * lane]     = ap0;
    shw[160 + 3 * lane + 1] = ap1;
    shw[160 + 3 * lane + 2] = ap2;
    __syncwarp();

    float* op = out + (size_t)node * OUT_ROW;
#pragma unroll
    for (int j = 0; j < 8; j++)
        op[32 * j + lane] = shw[32 * j + lane];
}

// ---------------------------------------------------------------------------
// Launch
// ---------------------------------------------------------------------------
extern "C" void kernel_launch(void* const* d_in, const int* in_sizes, int n_in,
                              void* d_out, int out_size) {
    const float* node_feats = (const float*)d_in[0];
    const float* edge_attrs = (const float*)d_in[1];
    const int*   senders    = (const int*)d_in[2];
    const int*   receivers  = (const int*)d_in[3];
    const float* w0         = (const float*)d_in[4];
    const float* w1         = (const float*)d_in[5];
    const float* w2         = (const float*)d_in[6];
    float* out = (float*)d_out;
    const int E = in_sizes[1] / 4;          // edge_attrs is E x 4
    const int n_nodes = out_size / OUT_ROW; // output is n_nodes x 256
    const int nb = (n_nodes + SCAN_B - 1) / SCAN_B;   // <= 64

    build_table_kernel<<<TABLE_N, 128>>>(w0, w1, w2);
    pack_table_kernel<<<(TABLE_N * 32 + 255) / 256, 256>>>();
    transpose_nodes_kernel<<<(n_nodes + 7) / 8, 256>>>(node_feats, n_nodes);
    zero_counts_kernel<<<(n_nodes + 255) / 256, 256>>>(n_nodes);
    hist_kernel<<<(E + 255) / 256, 256>>>(receivers, E);
    scan1_kernel<<<nb, SCAN_B>>>(n_nodes);
    scan2_kernel<<<1, MAX_SCAN_BLOCKS>>>(nb);
    scan3_kernel<<<(n_nodes + 255) / 256, 256>>>(n_nodes, E);
    scatter_kernel<<<(E + 255) / 256, 256>>>(senders, receivers,
                                             (const float4*)edge_attrs, E);
    aggregate_kernel<<<(n_nodes + 7) / 8, 256>>>(out, n_nodes);
}

// round 5
// speedup vs baseline: 1.0567x; 1.0567x over previous
#include <cuda_runtime.h>
#include <cuda_fp16.h>

#define N_NODES_MAX 50000
#define N_EDGES_MAX 800000
#define NODE_ROW 128          // 4*MUL floats per node
#define OUT_ROW 256           // output floats per node
#define TABLE_N 512
#define XMIN (-8.0f)
#define XMAX (8.0f)
#define INV_SQRT3 0.57735026918962576f
#define OUT_SCALE 0.25f       // 1/sqrt(16)
#define SCAN_B 1024
#define MAX_SCAN_BLOCKS 64

// 32B-aligned edge record: float4 attrs + sender id in ONE L2 sector.
struct __align__(32) ERec {
    float4 ea;
    int    s;
    int    pad0, pad1, pad2;
};

// ---- static device scratch (no allocations allowed) ----
__device__ float4 g_vals4[TABLE_N * 32];        // per (i0,lane): {m_s,m_t,m_v,m_p}
__device__ uint2  g_slp4[TABLE_N * 32];         // per (i0,lane): 4 x fp16 slopes
__device__ float4 g_nodeT[N_NODES_MAX * 32];    // per (node,lane): {s, v0, v1, v2}
__device__ int    g_counts[N_NODES_MAX];
__device__ int    g_rowptr[N_NODES_MAX + 1];
__device__ int    g_cursor[N_NODES_MAX];
__device__ int    g_btot[MAX_SCAN_BLOCKS];
__device__ ERec   g_erec[N_EDGES_MAX];          // edge payload sorted by receiver

__device__ __forceinline__ float swishf(float z) {
    return z / (1.0f + expf(-z));
}

// ---------------------------------------------------------------------------
// Fused preprocessing megakernel. Grid sections (all independent):
//   [0, TABLE_N)                : table build + pack (block b -> rows b, b+1)
//   [TABLE_N, TABLE_N+NT)       : node transpose (8 nodes / block)
//   [TABLE_N+NT, ...)           : histogram of receivers (4 edges / thread)
// g_counts is zeroed by cudaMemsetAsync before this kernel.
// ---------------------------------------------------------------------------
__global__ void fused_pre_kernel(const float* __restrict__ w0,
                                 const float* __restrict__ w1,
                                 const float* __restrict__ w2,
                                 const float* __restrict__ nf,
                                 const int* __restrict__ receivers,
                                 int n_nodes, int E, int nt_blocks) {
    const int b = blockIdx.x;

    if (b < TABLE_N) {
        // ---- table build (rows b and min(b+1, TABLE_N-1)) + pack ----
        __shared__ float h0[2][64];
        __shared__ float h1[2][64];
        __shared__ float mix[2][128];
        const int half = threadIdx.x >> 7;           // 0 or 1
        const int t = threadIdx.x & 127;
        const int row = min(b + half, TABLE_N - 1);
        const float dx = (XMAX - XMIN) / (float)(TABLE_N - 1);
        const float x = XMIN + dx * (float)row;

        if (t < 64) h0[half][t] = swishf(x * w0[t]);
        __syncthreads();
        if (t < 64) {
            float acc = 0.0f;
#pragma unroll 8
            for (int i = 0; i < 64; i++) acc = fmaf(h0[half][i], w1[i * 64 + t], acc);
            h1[half][t] = swishf(acc * 0.125f);
        }
        __syncthreads();
        {
            float acc = 0.0f;
#pragma unroll 8
            for (int i = 0; i < 64; i++) acc = fmaf(h1[half][i], w2[i * 128 + t], acc);
            float m = acc * 0.125f * OUT_SCALE;
            if (t >= 32 && t < 64) m *= INV_SQRT3;   // tp_0e factor folded
            mix[half][t] = m;
        }
        __syncthreads();
        if (threadIdx.x < 32) {
            const int lane = threadIdx.x;
            float vs = mix[0][lane],      vt = mix[0][32 + lane];
            float vv = mix[0][64 + lane], vp = mix[0][96 + lane];
            float ds = mix[1][lane] - vs,      dt = mix[1][32 + lane] - vt;
            float dv = mix[1][64 + lane] - vv, dp = mix[1][96 + lane] - vp;
            g_vals4[b * 32 + lane] = make_float4(vs, vt, vv, vp);
            half2 lo = __floats2half2_rn(ds, dt);
            half2 hi = __floats2half2_rn(dv, dp);
            uint2 u;
            u.x = *(unsigned int*)&lo;
            u.y = *(unsigned int*)&hi;
            g_slp4[b * 32 + lane] = u;
        }
        return;
    }

    if (b < TABLE_N + nt_blocks) {
        // ---- node transpose: nodeT[n][lane] = {s, v0, v1, v2} ----
        const int wid  = threadIdx.x >> 5;
        const int lane = threadIdx.x & 31;
        const int node = (b - TABLE_N) * 8 + wid;
        if (node >= n_nodes) return;
        const float* r = nf + (size_t)node * NODE_ROW;
        float s  = __ldg(r + lane);
        float v0 = __ldg(r + 32 + 3 * lane);
        float v1 = __ldg(r + 33 + 3 * lane);
        float v2 = __ldg(r + 34 + 3 * lane);
        g_nodeT[(size_t)node * 32 + lane] = make_float4(s, v0, v1, v2);
        return;
    }

    // ---- histogram: 4 edges per thread, vectorized read ----
    const int idx = (b - TABLE_N - nt_blocks) * (256 * 4) + threadIdx.x * 4;
    if (idx + 3 < E) {
        int4 r4 = __ldg((const int4*)(receivers + idx));
        atomicAdd(&g_counts[r4.x], 1);
        atomicAdd(&g_counts[r4.y], 1);
        atomicAdd(&g_counts[r4.z], 1);
        atomicAdd(&g_counts[r4.w], 1);
    } else {
        for (int e = idx; e < E; e++) atomicAdd(&g_counts[receivers[e]], 1);
    }
}

// ---------------------------------------------------------------------------
// 3-phase exclusive scan over g_counts -> g_rowptr / g_cursor
// ---------------------------------------------------------------------------
__global__ void scan1_kernel(int n_nodes) {
    __shared__ int s[SCAN_B];
    const int t = threadIdx.x;
    const int gid = blockIdx.x * SCAN_B + t;
    int v = (gid < n_nodes) ? g_counts[gid] : 0;
    s[t] = v;
    __syncthreads();
    for (int d = 1; d < SCAN_B; d <<= 1) {
        int x = (t >= d) ? s[t - d] : 0;
        __syncthreads();
        s[t] += x;
        __syncthreads();
    }
    if (gid < n_nodes) g_rowptr[gid] = s[t] - v;     // block-local exclusive
    if (t == SCAN_B - 1) g_btot[blockIdx.x] = s[t];
}

__global__ void scan2_kernel(int nb) {
    __shared__ int s[MAX_SCAN_BLOCKS];
    const int t = threadIdx.x;
    int v = (t < nb) ? g_btot[t] : 0;
    s[t] = v;
    __syncthreads();
    for (int d = 1; d < MAX_SCAN_BLOCKS; d <<= 1) {
        int x = (t >= d) ? s[t - d] : 0;
        __syncthreads();
        s[t] += x;
        __syncthreads();
    }
    if (t < nb) g_btot[t] = s[t] - v;                // exclusive
}

__global__ void scan3_kernel(int n_nodes, int E) {
    int gid = blockIdx.x * blockDim.x + threadIdx.x;
    if (gid < n_nodes) {
        int r = g_rowptr[gid] + g_btot[gid >> 10];
        g_rowptr[gid] = r;
        g_cursor[gid] = r;
    }
    if (gid == 0) g_rowptr[n_nodes] = E;
}

// ---------------------------------------------------------------------------
// Scatter: payload sort by receiver. One 32B record per edge => the random
// write touches a single L2 sector.
// ---------------------------------------------------------------------------
__global__ void scatter_kernel(const int* __restrict__ senders,
                               const int* __restrict__ receivers,
                               const float4* __restrict__ edge_attrs,
                               int E) {
    int e = blockIdx.x * blockDim.x + threadIdx.x;
    if (e < E) {
        int pos = atomicAdd(&g_cursor[receivers[e]], 1);
        ERec* rec = &g_erec[pos];
        rec->ea = __ldg(&edge_attrs[e]);
        rec->s  = __ldg(&senders[e]);
    }
}

// ---------------------------------------------------------------------------
// Aggregate: one warp per receiver node. Lane l owns channel l. Per edge:
// 1 broadcast 32B record + 1 LDG.128 node gather + LDG.128/LDG.64 table.
// Register accumulation, one shared transpose, 8 coalesced stores.
// ---------------------------------------------------------------------------
__global__ void aggregate_kernel(float* __restrict__ out, int n_nodes) {
    __shared__ float sh[8][OUT_ROW];               // 8 warps x 256 floats = 8 KB
    const int wid  = threadIdx.x >> 5;
    const int lane = threadIdx.x & 31;
    const int node = blockIdx.x * 8 + wid;
    if (node >= n_nodes) return;

    const int start = __ldg(&g_rowptr[node]);
    const int end   = __ldg(&g_rowptr[node + 1]);

    float a_s = 0.f, a_t = 0.f;
    float av0 = 0.f, av1 = 0.f, av2 = 0.f;
    float ap0 = 0.f, ap1 = 0.f, ap2 = 0.f;

    const float inv_dx = (float)(TABLE_N - 1) / (XMAX - XMIN);

#pragma unroll 2
    for (int i = start; i < end; i++) {
        const float4 ea = __ldg(&g_erec[i].ea);    // ea.x = ea0; (y,z,w) = ea1
        const int s = __ldg(&g_erec[i].s);

        const float4 nf = __ldg(&g_nodeT[(size_t)s * 32 + lane]);
        const float s_e = nf.x, v0 = nf.y, v1 = nf.z, v2 = nf.w;

        float tt = (ea.x - XMIN) * inv_dx;
        tt = fminf(fmaxf(tt, 0.0f), (float)(TABLE_N - 1) - 1.0e-3f);
        const int i0 = (int)tt;
        const float f = tt - (float)i0;

        const float4 mv = __ldg(&g_vals4[i0 * 32 + lane]);
        const uint2  su = __ldg(&g_slp4[i0 * 32 + lane]);
        const float2 slo = __half22float2(*(const half2*)&su.x);
        const float2 shi = __half22float2(*(const half2*)&su.y);

        const float m_s = fmaf(slo.x, f, mv.x);
        const float m_t = fmaf(slo.y, f, mv.y);
        const float m_v = fmaf(shi.x, f, mv.z);
        const float m_p = fmaf(shi.y, f, mv.w);

        a_s = fmaf(s_e, m_s, a_s);
        const float dot3 = fmaf(v0, ea.y, fmaf(v1, ea.z, v2 * ea.w));
        a_t = fmaf(dot3, m_t, a_t);                // INV_SQRT3 folded into table
        av0 = fmaf(v0, m_v, av0);
        av1 = fmaf(v1, m_v, av1);
        av2 = fmaf(v2, m_v, av2);
        const float sp = s_e * m_p;
        ap0 = fmaf(sp, ea.y, ap0);
        ap1 = fmaf(sp, ea.z, ap1);
        ap2 = fmaf(sp, ea.w, ap2);
    }

    // Transpose once per node via shared (stride-3 stores: conflict-free)
    float* shw = sh[wid];
    shw[lane]               = a_s;
    shw[32 + lane]          = a_t;
    shw[64  + 3 * lane]     = av0;
    shw[64  + 3 * lane + 1] = av1;
    shw[64  + 3 * lane + 2] = av2;
    shw[160 + 3 * lane]     = ap0;
    shw[160 + 3 * lane + 1] = ap1;
    shw[160 + 3 * lane + 2] = ap2;
    __syncwarp();

    float* op = out + (size_t)node * OUT_ROW;
#pragma unroll
    for (int j = 0; j < 8; j++)
        op[32 * j + lane] = shw[32 * j + lane];
}

// ---------------------------------------------------------------------------
// Launch
// ---------------------------------------------------------------------------
extern "C" void kernel_launch(void* const* d_in, const int* in_sizes, int n_in,
                              void* d_out, int out_size) {
    const float* node_feats = (const float*)d_in[0];
    const float* edge_attrs = (const float*)d_in[1];
    const int*   senders    = (const int*)d_in[2];
    const int*   receivers  = (const int*)d_in[3];
    const float* w0         = (const float*)d_in[4];
    const float* w1         = (const float*)d_in[5];
    const float* w2         = (const float*)d_in[6];
    float* out = (float*)d_out;
    const int E = in_sizes[1] / 4;          // edge_attrs is E x 4
    const int n_nodes = out_size / OUT_ROW; // output is n_nodes x 256
    const int nb = (n_nodes + SCAN_B - 1) / SCAN_B;   // <= 64
    const int nt_blocks = (n_nodes + 7) / 8;
    const int hist_blocks = (E + 1023) / 1024;

    void* counts_ptr = nullptr;
    cudaGetSymbolAddress(&counts_ptr, g_counts);
    cudaMemsetAsync(counts_ptr, 0, (size_t)n_nodes * sizeof(int));

    fused_pre_kernel<<<TABLE_N + nt_blocks + hist_blocks, 256>>>(
        w0, w1, w2, node_feats, receivers, n_nodes, E, nt_blocks);
    scan1_kernel<<<nb, SCAN_B>>>(n_nodes);
    scan2_kernel<<<1, MAX_SCAN_BLOCKS>>>(nb);
    scan3_kernel<<<(n_nodes + 255) / 256, 256>>>(n_nodes, E);
    scatter_kernel<<<(E + 255) / 256, 256>>>(senders, receivers,
                                             (const float4*)edge_attrs, E);
    aggregate_kernel<<<(n_nodes + 7) / 8, 256>>>(out, n_nodes);
}